// round 1
// baseline (speedup 1.0000x reference)
#include <cuda_runtime.h>
#include <cuda_bf16.h>
#include <math.h>

// ---------------------------------------------------------------------------
// MetaMamba single-step decode, B=256, d_model=2048, d_inner=8192, d_state=16
// Inputs (metadata order):
//  0 x           (256,1,2048)
//  1 conv_state  (256,8192,4)
//  2 ssm_state   (256,8192,16)
//  3 W_in        (16384,2048)
//  4 conv_w      (8192,4)
//  5 conv_b      (8192)
//  6 W_xproj     (160,8192)
//  7 W_dt        (8192,128)
//  8 b_dt        (8192)
//  9 A_log       (8192,16)
// 10 D_param     (8192)
// 11 W_out       (2048,8192)
// Output: concat( out(256*2048), conv_state(256*8192*4), ssm_state(256*8192*16) )
// ---------------------------------------------------------------------------

#define B_    256
#define DM    2048
#define DI    8192
#define DS    16
#define DTR   128
#define NXDB  160          // DT_RANK + 2*D_STATE
#define DXZ   (2*DI)       // 16384
#define KSPLIT2 16

// scratch (device globals -- no runtime allocation allowed)
__device__ float g_xz[(size_t)B_ * DXZ];         // xz = x @ W_in^T
__device__ float g_xc[(size_t)B_ * DI];          // silu(conv(x))
__device__ float g_part[(size_t)KSPLIT2 * B_ * NXDB]; // split-K partials for GEMM2
__device__ float g_xdb[(size_t)B_ * NXDB];       // x_db
__device__ float g_dtpre[(size_t)B_ * DI];       // dt @ W_dt^T (pre-softplus, no bias)
__device__ float g_y[(size_t)B_ * DI];           // y before W_out

// ---- packed fp32x2 helpers (Blackwell FFMA2) ------------------------------
__device__ __forceinline__ unsigned long long ffma2(unsigned long long a,
                                                    unsigned long long b,
                                                    unsigned long long c) {
    unsigned long long d;
    asm("fma.rn.f32x2 %0, %1, %2, %3;" : "=l"(d) : "l"(a), "l"(b), "l"(c));
    return d;
}
__device__ __forceinline__ float2 unpack2(unsigned long long v) {
    float2 f;
    asm("mov.b64 {%0, %1}, %2;" : "=f"(f.x), "=f"(f.y) : "l"(v));
    return f;
}

// ---------------------------------------------------------------------------
// Generic NT SGEMM:  C[M,N] = A[M,K] * B[N,K]^T   (both K-contiguous)
// BM=64 fixed, BK=16 fixed, 256 threads, TM=4 rows per thread.
// BN/TN select 128/8 or 64/4. NG enables N-bounds guards (for N=160).
// grid = (ceil(N/BN), M/64, kSplits). Split-K writes partials at
// C + z*M*ldc (caller provides a partial buffer when gridDim.z > 1).
// ---------------------------------------------------------------------------
template<int BN, int TN, bool NG>
__global__ void __launch_bounds__(256)
sgemm_nt(const float* __restrict__ A, int lda,
         const float* __restrict__ Bm, int ldb,
         float* __restrict__ C, int ldc,
         int M, int N, int K, int kPerSplit)
{
    constexpr int BM = 64;
    constexpr int BK = 16;
    constexpr int TM = 4;
    constexpr int APAD = 2 * BM + 8;   // rows padded to dodge STS bank conflicts
    constexpr int BPAD = BN + 8;

    __shared__ __align__(16) float As[BK][APAD];  // m-values duplicated in pairs
    __shared__ __align__(16) float Bs[BK][BPAD];

    const int n0 = blockIdx.x * BN;
    const int m0 = blockIdx.y * BM;
    const int kStart = blockIdx.z * kPerSplit;
    int kEnd = kStart + kPerSplit;
    if (kEnd > K) kEnd = K;
    C += (size_t)blockIdx.z * (size_t)M * (size_t)ldc;

    const int tx = threadIdx.x % (BN / TN);
    const int ty = threadIdx.x / (BN / TN);

    unsigned long long acc[TM][TN / 2];
#pragma unroll
    for (int i = 0; i < TM; ++i)
#pragma unroll
        for (int j = 0; j < TN / 2; ++j) acc[i][j] = 0ull;

    const int ar = threadIdx.x >> 2;          // 0..63
    const int ac = (threadIdx.x & 3) << 2;    // 0,4,8,12

    for (int k0 = kStart; k0 < kEnd; k0 += BK) {
        // load A tile (64 x 16), store duplicated: As[k][2m]=As[k][2m+1]=a
        float4 av = *(const float4*)(A + (size_t)(m0 + ar) * lda + (k0 + ac));
        As[ac + 0][2 * ar] = av.x;  As[ac + 0][2 * ar + 1] = av.x;
        As[ac + 1][2 * ar] = av.y;  As[ac + 1][2 * ar + 1] = av.y;
        As[ac + 2][2 * ar] = av.z;  As[ac + 2][2 * ar + 1] = av.z;
        As[ac + 3][2 * ar] = av.w;  As[ac + 3][2 * ar + 1] = av.w;
        // load B tile (BN x 16)
#pragma unroll
        for (int i = 0; i < BN / 64; ++i) {
            int idx = threadIdx.x + i * 256;
            int br = idx >> 2;
            int bc = (idx & 3) << 2;
            float4 bv = make_float4(0.f, 0.f, 0.f, 0.f);
            if (!NG || (n0 + br) < N)
                bv = *(const float4*)(Bm + (size_t)(n0 + br) * ldb + (k0 + bc));
            Bs[bc + 0][br] = bv.x;
            Bs[bc + 1][br] = bv.y;
            Bs[bc + 2][br] = bv.z;
            Bs[bc + 3][br] = bv.w;
        }
        __syncthreads();

#pragma unroll
        for (int kk = 0; kk < BK; ++kk) {
            unsigned long long areg[TM], breg[TN / 2];
#pragma unroll
            for (int i = 0; i < TM; ++i)
                areg[i] = *(const unsigned long long*)&As[kk][2 * (ty * TM + i)];
#pragma unroll
            for (int j = 0; j < TN / 2; ++j)
                breg[j] = *(const unsigned long long*)&Bs[kk][tx * TN + 2 * j];
#pragma unroll
            for (int i = 0; i < TM; ++i)
#pragma unroll
                for (int j = 0; j < TN / 2; ++j)
                    acc[i][j] = ffma2(areg[i], breg[j], acc[i][j]);
        }
        __syncthreads();
    }

    // store
#pragma unroll
    for (int i = 0; i < TM; ++i) {
        int m = m0 + ty * TM + i;
#pragma unroll
        for (int j = 0; j < TN / 2; ++j) {
            int n = n0 + tx * TN + 2 * j;
            float2 v = unpack2(acc[i][j]);
            if (NG) {
                if (n < N)     C[(size_t)m * ldc + n]     = v.x;
                if (n + 1 < N) C[(size_t)m * ldc + n + 1] = v.y;
            } else {
                *(float2*)&C[(size_t)m * ldc + n] = v;
            }
        }
    }
}

// ---------------------------------------------------------------------------
// conv update + silu: per (b,d) thread.
// ---------------------------------------------------------------------------
__global__ void __launch_bounds__(256)
conv_silu_kernel(const float* __restrict__ conv_state,
                 const float* __restrict__ conv_w,
                 const float* __restrict__ conv_b,
                 float* __restrict__ conv_out)
{
    int idx = blockIdx.x * 256 + threadIdx.x;      // b*DI + d
    int b = idx >> 13;
    int d = idx & (DI - 1);

    float4 cs = ((const float4*)conv_state)[idx];
    float  xi = g_xz[(size_t)b * DXZ + d];
    float4 w  = ((const float4*)conv_w)[d];

    float pre = cs.y * w.x + cs.z * w.y + cs.w * w.z + xi * w.w + conv_b[d];
    float sig = 1.f / (1.f + __expf(-pre));
    g_xc[idx] = pre * sig;

    ((float4*)conv_out)[idx] = make_float4(cs.y, cs.z, cs.w, xi);
}

// ---------------------------------------------------------------------------
// reduce split-K partials for x_db
// ---------------------------------------------------------------------------
__global__ void __launch_bounds__(256)
reduce_xdb_kernel()
{
    int i = blockIdx.x * 256 + threadIdx.x;
    if (i >= B_ * NXDB) return;
    float s = 0.f;
#pragma unroll
    for (int z = 0; z < KSPLIT2; ++z)
        s += g_part[(size_t)z * (B_ * NXDB) + i];
    g_xdb[i] = s;
}

// ---------------------------------------------------------------------------
// SSM state update + y; writes new ssm_state directly into d_out region.
// grid = (DI/256, B_)
// ---------------------------------------------------------------------------
__global__ void __launch_bounds__(256)
ssm_kernel(const float* __restrict__ ssm_state,
           const float* __restrict__ b_dt,
           const float* __restrict__ A_log,
           const float* __restrict__ D_param,
           float* __restrict__ ssm_out)
{
    const int b = blockIdx.y;
    const int d = blockIdx.x * 256 + threadIdx.x;

    __shared__ float sBC[2 * DS];   // Bm[16] then Cm[16]
    if (threadIdx.x < 2 * DS)
        sBC[threadIdx.x] = g_xdb[b * NXDB + DTR + threadIdx.x];
    __syncthreads();

    float u  = g_dtpre[(size_t)b * DI + d] + b_dt[d];
    float dt = (u > 20.f) ? u : log1pf(__expf(u));
    float xc = g_xc[(size_t)b * DI + d];
    float zz = g_xz[(size_t)b * DXZ + DI + d];

    const size_t so = ((size_t)b * DI + d) * DS;
    const float4* Al = (const float4*)(A_log + (size_t)d * DS);
    const float4* Ss = (const float4*)(ssm_state + so);
    float4*       So = (float4*)(ssm_out + so);

    float y = 0.f;
    const float xdt = xc * dt;
#pragma unroll
    for (int j = 0; j < 4; ++j) {
        float4 a4 = Al[j];
        float4 s4 = Ss[j];
        float4 o;
        o.x = s4.x * __expf(-dt * __expf(a4.x)) + xdt * sBC[4 * j + 0];
        o.y = s4.y * __expf(-dt * __expf(a4.y)) + xdt * sBC[4 * j + 1];
        o.z = s4.z * __expf(-dt * __expf(a4.z)) + xdt * sBC[4 * j + 2];
        o.w = s4.w * __expf(-dt * __expf(a4.w)) + xdt * sBC[4 * j + 3];
        y += o.x * sBC[DS + 4 * j + 0];
        y += o.y * sBC[DS + 4 * j + 1];
        y += o.z * sBC[DS + 4 * j + 2];
        y += o.w * sBC[DS + 4 * j + 3];
        So[j] = o;
    }
    y = (y + D_param[d] * xc);
    y *= zz / (1.f + __expf(-zz));       // * silu(z)
    g_y[(size_t)b * DI + d] = y;
}

// ---------------------------------------------------------------------------
extern "C" void kernel_launch(void* const* d_in, const int* in_sizes, int n_in,
                              void* d_out, int out_size)
{
    const float* x          = (const float*)d_in[0];
    const float* conv_state = (const float*)d_in[1];
    const float* ssm_state  = (const float*)d_in[2];
    const float* W_in       = (const float*)d_in[3];
    const float* conv_w     = (const float*)d_in[4];
    const float* conv_b     = (const float*)d_in[5];
    const float* W_xproj    = (const float*)d_in[6];
    const float* W_dt       = (const float*)d_in[7];
    const float* b_dt       = (const float*)d_in[8];
    const float* A_log      = (const float*)d_in[9];
    const float* D_param    = (const float*)d_in[10];
    const float* W_out      = (const float*)d_in[11];

    float* out      = (float*)d_out;                        // (256,1,2048)
    float* conv_out = out + (size_t)B_ * DM;                // (256,8192,4)
    float* ssm_out  = conv_out + (size_t)B_ * DI * 4;       // (256,8192,16)

    float *p_xz, *p_xc, *p_part, *p_xdb, *p_dtpre, *p_y;
    cudaGetSymbolAddress((void**)&p_xz,    g_xz);
    cudaGetSymbolAddress((void**)&p_xc,    g_xc);
    cudaGetSymbolAddress((void**)&p_part,  g_part);
    cudaGetSymbolAddress((void**)&p_xdb,   g_xdb);
    cudaGetSymbolAddress((void**)&p_dtpre, g_dtpre);
    cudaGetSymbolAddress((void**)&p_y,     g_y);

    // 1) xz = x @ W_in^T : M=256, N=16384, K=2048
    {
        dim3 grid(DXZ / 128, B_ / 64, 1);
        sgemm_nt<128, 8, false><<<grid, 256>>>(x, DM, W_in, DM,
                                               p_xz, DXZ, B_, DXZ, DM, DM);
    }
    // 2) conv shift + silu  (also writes conv_state output)
    conv_silu_kernel<<<(B_ * DI) / 256, 256>>>(conv_state, conv_w, conv_b, conv_out);

    // 3) x_db = xc @ W_xproj^T : M=256, N=160, K=8192, split-K=16
    {
        dim3 grid(2, B_ / 64, KSPLIT2);
        sgemm_nt<128, 8, true><<<grid, 256>>>(p_xc, DI, W_xproj, DI,
                                              p_part, NXDB, B_, NXDB, DI, DI / KSPLIT2);
    }
    reduce_xdb_kernel<<<(B_ * NXDB + 255) / 256, 256>>>();

    // 4) dt_pre = dt_low @ W_dt^T : M=256, N=8192, K=128 (A has row stride 160)
    {
        dim3 grid(DI / 128, B_ / 64, 1);
        sgemm_nt<128, 8, false><<<grid, 256>>>(p_xdb, NXDB, W_dt, DTR,
                                               p_dtpre, DI, B_, DI, DTR, DTR);
    }
    // 5) SSM update (writes ssm_state output + y)
    {
        dim3 grid(DI / 256, B_);
        ssm_kernel<<<grid, 256>>>(ssm_state, b_dt, A_log, D_param, ssm_out);
    }
    // 6) out = y @ W_out^T : M=256, N=2048, K=8192  (BN=64 -> 128 blocks)
    {
        dim3 grid(DM / 64, B_ / 64, 1);
        sgemm_nt<64, 4, false><<<grid, 256>>>(p_y, DI, W_out, DI,
                                              out, DM, B_, DM, DI, DI);
    }
}

// round 2
// speedup vs baseline: 4.4599x; 4.4599x over previous
#include <cuda_runtime.h>
#include <cuda_bf16.h>
#include <math.h>
#include <stdint.h>

// ---------------------------------------------------------------------------
// MetaMamba single-step decode, B=256, d_model=2048, d_inner=8192, d_state=16
// GEMMs run on tensor cores: mma.sync m16n8k16 bf16 with hi/lo split
// (3 MMAs emulate fp32: ah*bh + ah*bl + al*bh, rel err ~4e-6).
// ---------------------------------------------------------------------------

#define B_    256
#define DM    2048
#define DI    8192
#define DS    16
#define DTR   128
#define NXDB  160          // DT_RANK + 2*D_STATE
#define DXZ   (2*DI)       // 16384

#define KSPLIT2 64         // split-K for GEMM2 (xc @ W_xproj^T)
#define KSPLIT5 8          // split-K for GEMM5 (y @ W_out^T)

// scratch (device globals -- no runtime allocation allowed)
__device__ float g_xz[(size_t)B_ * DXZ];          // xz = x @ W_in^T
__device__ float g_xc[(size_t)B_ * DI];           // silu(conv(x))
__device__ float g_part[(size_t)KSPLIT5 * B_ * DM]; // split-K partials (reused; max 4.2M floats)
__device__ float g_xdb[(size_t)B_ * NXDB];        // x_db
__device__ float g_dtpre[(size_t)B_ * DI];        // dt @ W_dt^T (pre-softplus, no bias)
__device__ float g_y[(size_t)B_ * DI];            // y before W_out

// ---------------------------------------------------------------------------
// helpers
// ---------------------------------------------------------------------------
__device__ __forceinline__ void ldmx4(uint32_t* r, uint32_t addr) {
    asm volatile("ldmatrix.sync.aligned.m8n8.x4.shared.b16 {%0,%1,%2,%3}, [%4];"
                 : "=r"(r[0]), "=r"(r[1]), "=r"(r[2]), "=r"(r[3]) : "r"(addr));
}
__device__ __forceinline__ void mma16816(float* c, const uint32_t* a, const uint32_t* b) {
    asm volatile("mma.sync.aligned.m16n8k16.row.col.f32.bf16.bf16.f32 "
                 "{%0,%1,%2,%3}, {%4,%5,%6,%7}, {%8,%9}, {%0,%1,%2,%3};"
                 : "+f"(c[0]), "+f"(c[1]), "+f"(c[2]), "+f"(c[3])
                 : "r"(a[0]), "r"(a[1]), "r"(a[2]), "r"(a[3]),
                   "r"(b[0]), "r"(b[1]));
}
// split two floats into packed-bf16 hi pair and lo pair (memory order: f0 low)
__device__ __forceinline__ void split2(float f0, float f1, uint32_t& hi, uint32_t& lo) {
    __nv_bfloat16 b0 = __float2bfloat16(f0), b1 = __float2bfloat16(f1);
    hi = ((uint32_t)__bfloat16_as_ushort(b1) << 16) | (uint32_t)__bfloat16_as_ushort(b0);
    float r0 = f0 - __bfloat162float(b0);
    float r1 = f1 - __bfloat162float(b1);
    __nv_bfloat16 c0 = __float2bfloat16(r0), c1 = __float2bfloat16(r1);
    lo = ((uint32_t)__bfloat16_as_ushort(c1) << 16) | (uint32_t)__bfloat16_as_ushort(c0);
}

// ---------------------------------------------------------------------------
// Tensor-core NT GEMM:  C[256,N] = A[256,K] * B[N,K]^T, fp32 in/out.
// BM=256 (whole batch), BN=128, BK=16, 512 threads (16 warps = 4m x 4n).
// grid = (N/128 rounded up, 1, kSplits); kSplit z writes partials at
// C + z*256*ldc.  NG enables N-bound guards (B rows + epilogue cols).
//
// smem (dynamic, 73728 B):
//  A planes: [buf(2)][hi/lo(2)]: 256 rows x pitch 24 bf16 (48B, ldmatrix-safe)
//  B planes: [buf(2)][hi/lo(2)]: 128 rows x pitch 24 bf16
// ---------------------------------------------------------------------------
#define GPITCH 24                     // bf16 elems per smem row (16 data + 8 pad)
#define A_PLANE (256 * GPITCH * 2)    // bytes per A plane = 12288
#define B_PLANE (128 * GPITCH * 2)    // bytes per B plane = 6144
#define OFF_A(buf, h) (((buf) * 2 + (h)) * A_PLANE)
#define OFF_B(buf, h) (4 * A_PLANE + ((buf) * 2 + (h)) * B_PLANE)
#define GSMEM_BYTES (4 * A_PLANE + 4 * B_PLANE)   // 73728

template<bool NG>
__global__ void __launch_bounds__(512)
gemm_bf16x2_nt(const float* __restrict__ A, int lda,
               const float* __restrict__ Bm, int ldb,
               float* __restrict__ C, int ldc,
               int N, int K, int kPerSplit)
{
    extern __shared__ char smem[];
    const uint32_t sbase = (uint32_t)__cvta_generic_to_shared(smem);

    const int tid  = threadIdx.x;
    const int lane = tid & 31;
    const int warp = tid >> 5;
    const int n0     = blockIdx.x * 128;
    const int kStart = blockIdx.z * kPerSplit;
    const int nIt    = kPerSplit / 16;
    C += (size_t)blockIdx.z * 256 * (size_t)ldc;

    // ---- loader indices ----
    const int lr = tid >> 2;            // 0..127
    const int lc = (tid & 3) * 4;       // 0,4,8,12
    const float* aPtr0 = A + (size_t)lr * lda + kStart + lc;          // row lr
    const float* aPtr1 = A + (size_t)(lr + 128) * lda + kStart + lc;  // row lr+128
    const float* bPtr  = Bm + (size_t)(n0 + lr) * ldb + kStart + lc;  // row n0+lr
    const bool bOK = !NG || (n0 + lr) < N;
    const uint32_t wOff = (uint32_t)(lr * GPITCH + lc) * 2;           // STS byte off in plane

    // ---- compute indices ----
    const int mBase = (warp >> 2) * 64;
    const int nBase = (warp & 3) * 32;
    const int aRow = lane & 15, aCol = (lane >> 4) * 8;
    const uint32_t aLane = (uint32_t)((mBase + aRow) * GPITCH + aCol) * 2;
    const int bRow = (lane & 7) + ((lane >> 4) << 3);
    const int bCol = ((lane >> 3) & 1) * 8;
    const uint32_t bLane = (uint32_t)((nBase + bRow) * GPITCH + bCol) * 2;

    float acc[4][4][4];
#pragma unroll
    for (int i = 0; i < 4; ++i)
#pragma unroll
        for (int j = 0; j < 4; ++j)
#pragma unroll
            for (int q = 0; q < 4; ++q) acc[i][j][q] = 0.f;

    // prologue load (k-tile 0)
    float4 av0 = *(const float4*)aPtr0;
    float4 av1 = *(const float4*)aPtr1;
    float4 bv  = bOK ? *(const float4*)bPtr : make_float4(0.f, 0.f, 0.f, 0.f);

    for (int it = 0; it < nIt; ++it) {
        const int buf = it & 1;
        // ---- convert + STS current staged regs into buf ----
        {
            uint32_t h0, h1, l0, l1;
            split2(av0.x, av0.y, h0, l0); split2(av0.z, av0.w, h1, l1);
            *(uint2*)(smem + OFF_A(buf, 0) + wOff) = make_uint2(h0, h1);
            *(uint2*)(smem + OFF_A(buf, 1) + wOff) = make_uint2(l0, l1);
            split2(av1.x, av1.y, h0, l0); split2(av1.z, av1.w, h1, l1);
            *(uint2*)(smem + OFF_A(buf, 0) + 128 * GPITCH * 2 + wOff) = make_uint2(h0, h1);
            *(uint2*)(smem + OFF_A(buf, 1) + 128 * GPITCH * 2 + wOff) = make_uint2(l0, l1);
            split2(bv.x, bv.y, h0, l0); split2(bv.z, bv.w, h1, l1);
            *(uint2*)(smem + OFF_B(buf, 0) + wOff) = make_uint2(h0, h1);
            *(uint2*)(smem + OFF_B(buf, 1) + wOff) = make_uint2(l0, l1);
        }
        __syncthreads();

        // ---- prefetch next k-tile ----
        if (it + 1 < nIt) {
            const int ko = (it + 1) * 16;
            av0 = *(const float4*)(aPtr0 + ko);
            av1 = *(const float4*)(aPtr1 + ko);
            bv  = bOK ? *(const float4*)(bPtr + ko) : make_float4(0.f, 0.f, 0.f, 0.f);
        }

        // ---- compute on buf ----
        uint32_t bH[2][4], bL[2][4];
#pragma unroll
        for (int p = 0; p < 2; ++p) {
            ldmx4(bH[p], sbase + OFF_B(buf, 0) + bLane + p * 768);
            ldmx4(bL[p], sbase + OFF_B(buf, 1) + bLane + p * 768);
        }
#pragma unroll
        for (int i = 0; i < 4; ++i) {
            uint32_t aH[4], aL[4];
            ldmx4(aH, sbase + OFF_A(buf, 0) + aLane + i * 768);
            ldmx4(aL, sbase + OFF_A(buf, 1) + aLane + i * 768);
#pragma unroll
            for (int j = 0; j < 4; ++j) {
                const uint32_t* bh = &bH[j >> 1][(j & 1) * 2];
                const uint32_t* bl = &bL[j >> 1][(j & 1) * 2];
                mma16816(acc[i][j], aH, bh);
                mma16816(acc[i][j], aL, bh);
                mma16816(acc[i][j], aH, bl);
            }
        }
    }

    // ---- epilogue ----
    const int g = lane >> 2, q = lane & 3;
#pragma unroll
    for (int i = 0; i < 4; ++i) {
#pragma unroll
        for (int j = 0; j < 4; ++j) {
            const int r0 = mBase + i * 16 + g;
            const int c0 = n0 + nBase + j * 8 + q * 2;
            if (!NG || c0 < N) {
                *(float2*)&C[(size_t)r0 * ldc + c0]       = make_float2(acc[i][j][0], acc[i][j][1]);
                *(float2*)&C[(size_t)(r0 + 8) * ldc + c0] = make_float2(acc[i][j][2], acc[i][j][3]);
            }
        }
    }
}

// ---------------------------------------------------------------------------
// generic split-K reduction: out[i] = sum_z part[z*n + i]
// ---------------------------------------------------------------------------
__global__ void __launch_bounds__(256)
reduce_sum_kernel(const float* __restrict__ part, float* __restrict__ out,
                  int n, int nz)
{
    int i = blockIdx.x * 256 + threadIdx.x;
    if (i >= n) return;
    float s = 0.f;
    for (int z = 0; z < nz; ++z) s += part[(size_t)z * n + i];
    out[i] = s;
}

// ---------------------------------------------------------------------------
// conv update + silu: per (b,d) thread.
// ---------------------------------------------------------------------------
__global__ void __launch_bounds__(256)
conv_silu_kernel(const float* __restrict__ conv_state,
                 const float* __restrict__ conv_w,
                 const float* __restrict__ conv_b,
                 float* __restrict__ conv_out)
{
    int idx = blockIdx.x * 256 + threadIdx.x;      // b*DI + d
    int b = idx >> 13;
    int d = idx & (DI - 1);

    float4 cs = ((const float4*)conv_state)[idx];
    float  xi = g_xz[(size_t)b * DXZ + d];
    float4 w  = ((const float4*)conv_w)[d];

    float pre = cs.y * w.x + cs.z * w.y + cs.w * w.z + xi * w.w + conv_b[d];
    float sig = 1.f / (1.f + __expf(-pre));
    g_xc[idx] = pre * sig;

    ((float4*)conv_out)[idx] = make_float4(cs.y, cs.z, cs.w, xi);
}

// ---------------------------------------------------------------------------
// SSM state update + y; writes new ssm_state directly into d_out region.
// grid = (DI/256, B_)
// ---------------------------------------------------------------------------
__global__ void __launch_bounds__(256)
ssm_kernel(const float* __restrict__ ssm_state,
           const float* __restrict__ b_dt,
           const float* __restrict__ A_log,
           const float* __restrict__ D_param,
           float* __restrict__ ssm_out)
{
    const int b = blockIdx.y;
    const int d = blockIdx.x * 256 + threadIdx.x;

    __shared__ float sBC[2 * DS];   // Bm[16] then Cm[16]
    if (threadIdx.x < 2 * DS)
        sBC[threadIdx.x] = g_xdb[b * NXDB + DTR + threadIdx.x];
    __syncthreads();

    float u  = g_dtpre[(size_t)b * DI + d] + b_dt[d];
    float dt = (u > 20.f) ? u : log1pf(__expf(u));
    float xc = g_xc[(size_t)b * DI + d];
    float zz = g_xz[(size_t)b * DXZ + DI + d];

    const size_t so = ((size_t)b * DI + d) * DS;
    const float4* Al = (const float4*)(A_log + (size_t)d * DS);
    const float4* Ss = (const float4*)(ssm_state + so);
    float4*       So = (float4*)(ssm_out + so);

    float y = 0.f;
    const float xdt = xc * dt;
#pragma unroll
    for (int j = 0; j < 4; ++j) {
        float4 a4 = Al[j];
        float4 s4 = Ss[j];
        float4 o;
        o.x = s4.x * __expf(-dt * __expf(a4.x)) + xdt * sBC[4 * j + 0];
        o.y = s4.y * __expf(-dt * __expf(a4.y)) + xdt * sBC[4 * j + 1];
        o.z = s4.z * __expf(-dt * __expf(a4.z)) + xdt * sBC[4 * j + 2];
        o.w = s4.w * __expf(-dt * __expf(a4.w)) + xdt * sBC[4 * j + 3];
        y += o.x * sBC[DS + 4 * j + 0];
        y += o.y * sBC[DS + 4 * j + 1];
        y += o.z * sBC[DS + 4 * j + 2];
        y += o.w * sBC[DS + 4 * j + 3];
        So[j] = o;
    }
    y = (y + D_param[d] * xc);
    y *= zz / (1.f + __expf(-zz));       // * silu(z)
    g_y[(size_t)b * DI + d] = y;
}

// ---------------------------------------------------------------------------
extern "C" void kernel_launch(void* const* d_in, const int* in_sizes, int n_in,
                              void* d_out, int out_size)
{
    const float* x          = (const float*)d_in[0];
    const float* conv_state = (const float*)d_in[1];
    const float* ssm_state  = (const float*)d_in[2];
    const float* W_in       = (const float*)d_in[3];
    const float* conv_w     = (const float*)d_in[4];
    const float* conv_b     = (const float*)d_in[5];
    const float* W_xproj    = (const float*)d_in[6];
    const float* W_dt       = (const float*)d_in[7];
    const float* b_dt       = (const float*)d_in[8];
    const float* A_log      = (const float*)d_in[9];
    const float* D_param    = (const float*)d_in[10];
    const float* W_out      = (const float*)d_in[11];

    float* out      = (float*)d_out;                        // (256,1,2048)
    float* conv_out = out + (size_t)B_ * DM;                // (256,8192,4)
    float* ssm_out  = conv_out + (size_t)B_ * DI * 4;       // (256,8192,16)

    float *p_xz, *p_xc, *p_part, *p_xdb, *p_dtpre, *p_y;
    cudaGetSymbolAddress((void**)&p_xz,    g_xz);
    cudaGetSymbolAddress((void**)&p_xc,    g_xc);
    cudaGetSymbolAddress((void**)&p_part,  g_part);
    cudaGetSymbolAddress((void**)&p_xdb,   g_xdb);
    cudaGetSymbolAddress((void**)&p_dtpre, g_dtpre);
    cudaGetSymbolAddress((void**)&p_y,     g_y);

    cudaFuncSetAttribute(gemm_bf16x2_nt<false>,
                         cudaFuncAttributeMaxDynamicSharedMemorySize, GSMEM_BYTES);
    cudaFuncSetAttribute(gemm_bf16x2_nt<true>,
                         cudaFuncAttributeMaxDynamicSharedMemorySize, GSMEM_BYTES);

    // 1) xz = x @ W_in^T : N=16384, K=2048 -> 128 CTAs
    gemm_bf16x2_nt<false><<<dim3(DXZ / 128, 1, 1), 512, GSMEM_BYTES>>>(
        x, DM, W_in, DM, p_xz, DXZ, DXZ, DM, DM);

    // 2) conv shift + silu  (also writes conv_state output)
    conv_silu_kernel<<<(B_ * DI) / 256, 256>>>(conv_state, conv_w, conv_b, conv_out);

    // 3) x_db = xc @ W_xproj^T : N=160, K=8192, split-K=64 -> 128 CTAs
    gemm_bf16x2_nt<true><<<dim3(2, 1, KSPLIT2), 512, GSMEM_BYTES>>>(
        p_xc, DI, W_xproj, DI, p_part, NXDB, NXDB, DI, DI / KSPLIT2);
    reduce_sum_kernel<<<(B_ * NXDB + 255) / 256, 256>>>(p_part, p_xdb, B_ * NXDB, KSPLIT2);

    // 4) dt_pre = dt_low @ W_dt^T : N=8192, K=128 (A row stride 160) -> 64 CTAs
    gemm_bf16x2_nt<false><<<dim3(DI / 128, 1, 1), 512, GSMEM_BYTES>>>(
        p_xdb, NXDB, W_dt, DTR, p_dtpre, DI, DI, DTR, DTR);

    // 5) SSM update (writes ssm_state output + y)
    ssm_kernel<<<dim3(DI / 256, B_), 256>>>(ssm_state, b_dt, A_log, D_param, ssm_out);

    // 6) out = y @ W_out^T : N=2048, K=8192, split-K=8 -> 128 CTAs
    gemm_bf16x2_nt<false><<<dim3(DM / 128, 1, KSPLIT5), 512, GSMEM_BYTES>>>(
        p_y, DI, W_out, DI, p_part, DM, DM, DI, DI / KSPLIT5);
    reduce_sum_kernel<<<(B_ * DM + 255) / 256, 256>>>(p_part, out, B_ * DM, KSPLIT5);
}